// round 7
// baseline (speedup 1.0000x reference)
#include <cuda_runtime.h>

#define BB 256
#define TT 1024
#define IDIM 2
#define HH 128
#define LL 4
#define MTOT (BB * TT)  // 262144

// Scratch (device globals: allocation-free). h ping-pong + xp stream.
// g_xp padded by 4 rows for the distance-3 register-ring prefetch overrun.
__device__ float g_h0[BB * TT * HH];
__device__ float g_h1[BB * TT * HH];
__device__ float g_xp[BB * TT * HH + 4 * HH];

typedef unsigned long long ull;

__device__ __forceinline__ void ffma2(ull& acc, ull a, ull b) {
    asm("fma.rn.f32x2 %0, %1, %2, %0;" : "+l"(acc) : "l"(a), "l"(b));
}
__device__ __forceinline__ ull add2(ull a, ull b) {
    ull d;
    asm("add.rn.f32x2 %0, %1, %2;" : "=l"(d) : "l"(a), "l"(b));
    return d;
}
__device__ __forceinline__ ull dup2(float a) {
    ull d;
    asm("mov.b64 %0, {%1, %1};" : "=l"(d) : "f"(a));
    return d;
}
__device__ __forceinline__ ull pack2(float x, float y) {
    ull d;
    asm("mov.b64 %0, {%1, %2};" : "=l"(d) : "f"(x), "f"(y));
    return d;
}

// ---------------- layer-0 input projection (I=2, trivial) ----------------
__global__ void proj0_kernel(const float* __restrict__ x,
                             const float* __restrict__ W0,
                             const float* __restrict__ bih,
                             const float* __restrict__ bhh,
                             float* __restrict__ xp) {
    int idx = blockIdx.x * 256 + threadIdx.x;
    int m = idx >> 7, j = idx & 127;
    float2 xv = *(const float2*)(x + m * 2);
    float2 w = *(const float2*)(W0 + j * 2);
    xp[idx] = fmaf(xv.x, w.x, fmaf(xv.y, w.y, bih[j] + bhh[j]));
}

// ---------------- input-projection GEMM for layers 1..3 ----------------
__global__ void __launch_bounds__(256, 2)
gemm_xp(const float* __restrict__ A, const float* __restrict__ W,
        const float* __restrict__ bih, const float* __restrict__ bhh,
        float* __restrict__ xp) {
    __shared__ float As[2][128][17];
    __shared__ float Bs[2][16][132];

    const int tid = threadIdx.x;
    const int m0 = blockIdx.x * 128;
    const int tx = tid & 15, ty = tid >> 4;
    const int n0 = tx * 8, mt = ty * 8;

    float4 av[2], bv[2];
#pragma unroll
    for (int it = 0; it < 2; it++) {
        int idx = tid + it * 256;
        int mm = idx >> 2, kq = idx & 3;
        av[it] = *(const float4*)(A + (size_t)(m0 + mm) * HH + kq * 4);
        bv[it] = *(const float4*)(W + (size_t)mm * HH + kq * 4);
    }
#pragma unroll
    for (int it = 0; it < 2; it++) {
        int idx = tid + it * 256;
        int mm = idx >> 2, kq = idx & 3;
        As[0][mm][kq * 4 + 0] = av[it].x;
        As[0][mm][kq * 4 + 1] = av[it].y;
        As[0][mm][kq * 4 + 2] = av[it].z;
        As[0][mm][kq * 4 + 3] = av[it].w;
        Bs[0][kq * 4 + 0][mm] = bv[it].x;
        Bs[0][kq * 4 + 1][mm] = bv[it].y;
        Bs[0][kq * 4 + 2][mm] = bv[it].z;
        Bs[0][kq * 4 + 3][mm] = bv[it].w;
    }
    __syncthreads();

    ull acc[8][4];
#pragma unroll
    for (int i = 0; i < 8; i++)
#pragma unroll
        for (int p = 0; p < 4; p++) acc[i][p] = 0ULL;

    int buf = 0;
    for (int kc = 0; kc < 8; kc++) {
        if (kc < 7) {
#pragma unroll
            for (int it = 0; it < 2; it++) {
                int idx = tid + it * 256;
                int mm = idx >> 2, kq = idx & 3;
                av[it] = *(const float4*)(A + (size_t)(m0 + mm) * HH +
                                          (kc + 1) * 16 + kq * 4);
                bv[it] = *(const float4*)(W + (size_t)mm * HH + (kc + 1) * 16 +
                                          kq * 4);
            }
        }
#pragma unroll
        for (int k = 0; k < 16; k++) {
            const ulonglong2* bp = (const ulonglong2*)&Bs[buf][k][n0];
            ulonglong2 u0 = bp[0], u1 = bp[1];
            ull ad[8];
#pragma unroll
            for (int i = 0; i < 8; i++) ad[i] = dup2(As[buf][mt + i][k]);
#pragma unroll
            for (int i = 0; i < 8; i++) {
                ffma2(acc[i][0], ad[i], u0.x);
                ffma2(acc[i][1], ad[i], u0.y);
                ffma2(acc[i][2], ad[i], u1.x);
                ffma2(acc[i][3], ad[i], u1.y);
            }
        }
        if (kc < 7) {
#pragma unroll
            for (int it = 0; it < 2; it++) {
                int idx = tid + it * 256;
                int mm = idx >> 2, kq = idx & 3;
                As[buf ^ 1][mm][kq * 4 + 0] = av[it].x;
                As[buf ^ 1][mm][kq * 4 + 1] = av[it].y;
                As[buf ^ 1][mm][kq * 4 + 2] = av[it].z;
                As[buf ^ 1][mm][kq * 4 + 3] = av[it].w;
                Bs[buf ^ 1][kq * 4 + 0][mm] = bv[it].x;
                Bs[buf ^ 1][kq * 4 + 1][mm] = bv[it].y;
                Bs[buf ^ 1][kq * 4 + 2][mm] = bv[it].z;
                Bs[buf ^ 1][kq * 4 + 3][mm] = bv[it].w;
            }
            __syncthreads();
            buf ^= 1;
        }
    }

    ull biasp[4];
#pragma unroll
    for (int p = 0; p < 4; p++) {
        float b0 = bih[n0 + 2 * p] + bhh[n0 + 2 * p];
        float b1 = bih[n0 + 2 * p + 1] + bhh[n0 + 2 * p + 1];
        biasp[p] = pack2(b0, b1);
    }
#pragma unroll
    for (int i = 0; i < 8; i++) {
        ull o0 = add2(acc[i][0], biasp[0]);
        ull o1 = add2(acc[i][1], biasp[1]);
        ull o2 = add2(acc[i][2], biasp[2]);
        ull o3 = add2(acc[i][3], biasp[3]);
        float* dst = xp + (size_t)(m0 + mt + i) * HH + n0;
        *(ulonglong2*)dst = make_ulonglong2(o0, o1);
        *(ulonglong2*)(dst + 4) = make_ulonglong2(o2, o3);
    }
}

// ---------------- recurrent scan (one layer, 2 batch rows/CTA) ----------
// h[t] = relu(xp[t] + Whh @ h[t-1]); xp precomputed (includes biases).
// Grid = 128 CTAs <= 148 SMs: exactly one CTA per SM, no co-residency
// contention. Thread j holds the FULL row Whh[j,:] in 64 packed f32x2
// registers and computes dot products for BOTH batch rows (8 independent
// FFMA2 chains reusing the same weights). One 4-warp __syncthreads per
// step. xp arrives via a distance-3 register ring per row.
// If fc_out != nullptr (final layer): skip hidden stores, fuse the FC
// (C=1) reduction on h[T-1] into the epilogue.
__global__ void __launch_bounds__(128, 1)
rnn_scan(const float* __restrict__ xp, float* __restrict__ out_h,
         const float* __restrict__ Whh, int store_all,
         const float* __restrict__ fcw, const float* __restrict__ fcb,
         float* __restrict__ fc_out) {
    __shared__ __align__(16) float hbuf[2][2][HH];  // [buf][row][j]
    __shared__ float red0[4], red1[4];

    const int j = threadIdx.x;
    const int b0 = blockIdx.x * 2;

    // full weight row, packed as 64 f32x2 pairs
    ull w[64];
    {
        const ull* wp = (const ull*)(Whh + j * HH);
#pragma unroll
        for (int i = 0; i < 64; i++) w[i] = wp[i];
    }

    hbuf[0][0][j] = 0.f;
    hbuf[0][1][j] = 0.f;

    const float* xp0 = xp + (size_t)b0 * TT * HH + j;
    const float* xp1 = xp0 + (size_t)TT * HH;
    float* o0 = out_h + (size_t)b0 * TT * HH + j;
    float* o1 = o0 + (size_t)TT * HH;

    float xq0a = xp0[0], xq0b = xp0[HH], xq0c = xp0[2 * HH];
    float xq1a = xp1[0], xq1b = xp1[HH], xq1c = xp1[2 * HH];
    const float* xf0 = xp0 + 3 * HH;  // padded scratch: safe overrun
    const float* xf1 = xp1 + 3 * HH;
    __syncthreads();

    float lh0 = 0.f, lh1 = 0.f;
    int buf = 0;
    for (int t = 0; t < TT; t++) {
        float xn0 = *xf0;  // xp(t+3): lands 3 steps out
        float xn1 = *xf1;
        xf0 += HH;
        xf1 += HH;

        const ulonglong2* hp0 = (const ulonglong2*)hbuf[buf][0];
        const ulonglong2* hp1 = (const ulonglong2*)hbuf[buf][1];
        ull a0 = 0ULL, a1 = 0ULL, a2 = 0ULL, a3 = 0ULL;
        ull c0 = 0ULL, c1 = 0ULL, c2 = 0ULL, c3 = 0ULL;
#pragma unroll
        for (int q = 0; q < 32; q += 2) {
            ulonglong2 u0 = hp0[q];      // broadcast LDS.128
            ulonglong2 u1 = hp0[q + 1];
            ulonglong2 v0 = hp1[q];
            ulonglong2 v1 = hp1[q + 1];
            ffma2(a0, u0.x, w[2 * q + 0]);
            ffma2(a1, u0.y, w[2 * q + 1]);
            ffma2(a2, u1.x, w[2 * q + 2]);
            ffma2(a3, u1.y, w[2 * q + 3]);
            ffma2(c0, v0.x, w[2 * q + 0]);
            ffma2(c1, v0.y, w[2 * q + 1]);
            ffma2(c2, v1.x, w[2 * q + 2]);
            ffma2(c3, v1.y, w[2 * q + 3]);
        }
        ull sa = add2(add2(a0, a1), add2(a2, a3));
        ull sc = add2(add2(c0, c1), add2(c2, c3));
        float2 fa = *(float2*)&sa;
        float2 fc = *(float2*)&sc;
        float h0 = fmaxf(fa.x + fa.y + xq0a, 0.f);
        float h1 = fmaxf(fc.x + fc.y + xq1a, 0.f);

        hbuf[buf ^ 1][0][j] = h0;
        hbuf[buf ^ 1][1][j] = h1;
        if (store_all) {
            o0[0] = h0;
            o1[0] = h1;
            o0 += HH;
            o1 += HH;
        }
        lh0 = h0;
        lh1 = h1;
        xq0a = xq0b; xq0b = xq0c; xq0c = xn0;
        xq1a = xq1b; xq1b = xq1c; xq1c = xn1;
        buf ^= 1;
        __syncthreads();
    }

    if (fc_out) {
        float v0 = lh0 * fcw[j];
        float v1 = lh1 * fcw[j];
#pragma unroll
        for (int o = 16; o > 0; o >>= 1) {
            v0 += __shfl_down_sync(0xffffffffu, v0, o);
            v1 += __shfl_down_sync(0xffffffffu, v1, o);
        }
        if ((j & 31) == 0) {
            red0[j >> 5] = v0;
            red1[j >> 5] = v1;
        }
        __syncthreads();
        if (j == 0) {
            fc_out[b0] = red0[0] + red0[1] + red0[2] + red0[3] + fcb[0];
            fc_out[b0 + 1] = red1[0] + red1[1] + red1[2] + red1[3] + fcb[0];
        }
    }
}

extern "C" void kernel_launch(void* const* d_in, const int* in_sizes, int n_in,
                              void* d_out, int out_size) {
    const float* x    = (const float*)d_in[0];  // [B,T,I]
    const float* Wih0 = (const float*)d_in[1];  // [H,I]
    const float* WihL = (const float*)d_in[2];  // [L-1,H,H]
    const float* Whh  = (const float*)d_in[3];  // [L,H,H]
    const float* bih  = (const float*)d_in[4];  // [L,H]
    const float* bhh  = (const float*)d_in[5];  // [L,H]
    const float* fcw  = (const float*)d_in[6];  // [C,H]
    const float* fcb  = (const float*)d_in[7];  // [C]
    float* out = (float*)d_out;                 // [B,C] = [256,1]

    float *h0, *h1, *xpb;
    cudaGetSymbolAddress((void**)&h0, g_h0);
    cudaGetSymbolAddress((void**)&h1, g_h1);
    cudaGetSymbolAddress((void**)&xpb, g_xp);

    const int HW = HH * HH;
    // layer 0
    proj0_kernel<<<(MTOT * HH) / 256, 256>>>(x, Wih0, bih, bhh, xpb);
    rnn_scan<<<BB / 2, 128>>>(xpb, h0, Whh + 0 * HW, 1, nullptr, nullptr,
                              nullptr);
    // layer 1
    gemm_xp<<<MTOT / 128, 256>>>(h0, WihL + 0 * HW, bih + 1 * HH, bhh + 1 * HH,
                                 xpb);
    rnn_scan<<<BB / 2, 128>>>(xpb, h1, Whh + 1 * HW, 1, nullptr, nullptr,
                              nullptr);
    // layer 2
    gemm_xp<<<MTOT / 128, 256>>>(h1, WihL + 1 * HW, bih + 2 * HH, bhh + 2 * HH,
                                 xpb);
    rnn_scan<<<BB / 2, 128>>>(xpb, h0, Whh + 2 * HW, 1, nullptr, nullptr,
                              nullptr);
    // layer 3: no hidden stores, FC fused on last timestep
    gemm_xp<<<MTOT / 128, 256>>>(h0, WihL + 2 * HW, bih + 3 * HH, bhh + 3 * HH,
                                 xpb);
    rnn_scan<<<BB / 2, 128>>>(xpb, h1, Whh + 3 * HW, 0, fcw, fcb, out);
}

// round 8
// speedup vs baseline: 1.2434x; 1.2434x over previous
#include <cuda_runtime.h>

#define BB 256
#define TT 1024
#define IDIM 2
#define HH 128
#define LL 4
#define MTOT (BB * TT)  // 262144

// Scratch (device globals: allocation-free).
// h scratch is TRANSPOSED: [B][H][T]. xp stays [B][T][H] (+pad for ring).
__device__ float g_h0[BB * HH * TT];
__device__ float g_h1[BB * HH * TT];
__device__ float g_xp[BB * TT * HH + 4 * HH];

typedef unsigned long long ull;

__device__ __forceinline__ void ffma2(ull& acc, ull a, ull b) {
    asm("fma.rn.f32x2 %0, %1, %2, %0;" : "+l"(acc) : "l"(a), "l"(b));
}
__device__ __forceinline__ ull add2(ull a, ull b) {
    ull d;
    asm("add.rn.f32x2 %0, %1, %2;" : "=l"(d) : "l"(a), "l"(b));
    return d;
}
__device__ __forceinline__ ull dup2(float a) {
    ull d;
    asm("mov.b64 %0, {%1, %1};" : "=l"(d) : "f"(a));
    return d;
}
__device__ __forceinline__ ull pack2(float x, float y) {
    ull d;
    asm("mov.b64 %0, {%1, %2};" : "=l"(d) : "f"(x), "f"(y));
    return d;
}
__device__ __forceinline__ void barrow(int id) {
    asm volatile("bar.sync %0, 128;" ::"r"(id) : "memory");
}

// ---------------- layer-0 input projection (I=2, trivial) ----------------
__global__ void proj0_kernel(const float* __restrict__ x,
                             const float* __restrict__ W0,
                             const float* __restrict__ bih,
                             const float* __restrict__ bhh,
                             float* __restrict__ xp) {
    int idx = blockIdx.x * 256 + threadIdx.x;
    int m = idx >> 7, j = idx & 127;
    float2 xv = *(const float2*)(x + m * 2);
    float2 w = *(const float2*)(W0 + j * 2);
    xp[idx] = fmaf(xv.x, w.x, fmaf(xv.y, w.y, bih[j] + bhh[j]));
}

// ---------------- input-projection GEMM for layers 1..3 ----------------
// xp[m, n] = sum_k At[b, k, t] * W[n, k] + bih[n] + bhh[n],  m = b*T + t.
// A is TRANSPOSED [B][H][T]; an m-tile of 128 is one b, one t-range.
// smem A tile stored [k][t] (STS.128, t-contiguous), W tile [k][n].
__global__ void __launch_bounds__(256, 2)
gemm_xp(const float* __restrict__ At, const float* __restrict__ W,
        const float* __restrict__ bih, const float* __restrict__ bhh,
        float* __restrict__ xp) {
    __shared__ float As[2][16][132];  // [k][t], pad keeps 16B row align
    __shared__ float Bs[2][16][132];  // [k][n]

    const int tid = threadIdx.x;
    const int m0 = blockIdx.x * 128;
    const int b_ = m0 >> 10;     // m0 / TT
    const int t0 = m0 & 1023;    // m0 % TT
    const int tx = tid & 15, ty = tid >> 4;
    const int n0 = tx * 8, mt = ty * 8;

    const float* Ab = At + (size_t)b_ * HH * TT + t0;

    float4 av[2], bv[2];
    // chunk 0 loads: A rows are k, contiguous in t
#pragma unroll
    for (int it = 0; it < 2; it++) {
        int idx = tid * 2 + it;          // 0..511
        int kl = idx >> 5, tq = idx & 31;
        av[it] = *(const float4*)(Ab + (size_t)kl * TT + tq * 4);
        int jdx = tid + it * 256;
        int mm = jdx >> 2, kq = jdx & 3;
        bv[it] = *(const float4*)(W + (size_t)mm * HH + kq * 4);
    }
#pragma unroll
    for (int it = 0; it < 2; it++) {
        int idx = tid * 2 + it;
        int kl = idx >> 5, tq = idx & 31;
        *(float4*)&As[0][kl][tq * 4] = av[it];
        int jdx = tid + it * 256;
        int mm = jdx >> 2, kq = jdx & 3;
        Bs[0][kq * 4 + 0][mm] = bv[it].x;
        Bs[0][kq * 4 + 1][mm] = bv[it].y;
        Bs[0][kq * 4 + 2][mm] = bv[it].z;
        Bs[0][kq * 4 + 3][mm] = bv[it].w;
    }
    __syncthreads();

    ull acc[8][4];
#pragma unroll
    for (int i = 0; i < 8; i++)
#pragma unroll
        for (int p = 0; p < 4; p++) acc[i][p] = 0ULL;

    int buf = 0;
    for (int kc = 0; kc < 8; kc++) {
        if (kc < 7) {
#pragma unroll
            for (int it = 0; it < 2; it++) {
                int idx = tid * 2 + it;
                int kl = idx >> 5, tq = idx & 31;
                av[it] = *(const float4*)(Ab + (size_t)((kc + 1) * 16 + kl) * TT +
                                          tq * 4);
                int jdx = tid + it * 256;
                int mm = jdx >> 2, kq = jdx & 3;
                bv[it] = *(const float4*)(W + (size_t)mm * HH + (kc + 1) * 16 +
                                          kq * 4);
            }
        }
#pragma unroll
        for (int k = 0; k < 16; k++) {
            const ulonglong2* bp = (const ulonglong2*)&Bs[buf][k][n0];
            ulonglong2 u0 = bp[0], u1 = bp[1];
            float4 am0 = *(const float4*)&As[buf][k][mt];
            float4 am1 = *(const float4*)&As[buf][k][mt + 4];
            ull ad[8];
            ad[0] = dup2(am0.x); ad[1] = dup2(am0.y);
            ad[2] = dup2(am0.z); ad[3] = dup2(am0.w);
            ad[4] = dup2(am1.x); ad[5] = dup2(am1.y);
            ad[6] = dup2(am1.z); ad[7] = dup2(am1.w);
#pragma unroll
            for (int i = 0; i < 8; i++) {
                ffma2(acc[i][0], ad[i], u0.x);
                ffma2(acc[i][1], ad[i], u0.y);
                ffma2(acc[i][2], ad[i], u1.x);
                ffma2(acc[i][3], ad[i], u1.y);
            }
        }
        if (kc < 7) {
#pragma unroll
            for (int it = 0; it < 2; it++) {
                int idx = tid * 2 + it;
                int kl = idx >> 5, tq = idx & 31;
                *(float4*)&As[buf ^ 1][kl][tq * 4] = av[it];
                int jdx = tid + it * 256;
                int mm = jdx >> 2, kq = jdx & 3;
                Bs[buf ^ 1][kq * 4 + 0][mm] = bv[it].x;
                Bs[buf ^ 1][kq * 4 + 1][mm] = bv[it].y;
                Bs[buf ^ 1][kq * 4 + 2][mm] = bv[it].z;
                Bs[buf ^ 1][kq * 4 + 3][mm] = bv[it].w;
            }
            __syncthreads();
            buf ^= 1;
        }
    }

    ull biasp[4];
#pragma unroll
    for (int p = 0; p < 4; p++) {
        float b0 = bih[n0 + 2 * p] + bhh[n0 + 2 * p];
        float b1 = bih[n0 + 2 * p + 1] + bhh[n0 + 2 * p + 1];
        biasp[p] = pack2(b0, b1);
    }
#pragma unroll
    for (int i = 0; i < 8; i++) {
        ull o0 = add2(acc[i][0], biasp[0]);
        ull o1 = add2(acc[i][1], biasp[1]);
        ull o2 = add2(acc[i][2], biasp[2]);
        ull o3 = add2(acc[i][3], biasp[3]);
        float* dst = xp + (size_t)(m0 + mt + i) * HH + n0;
        *(ulonglong2*)dst = make_ulonglong2(o0, o1);
        *(ulonglong2*)(dst + 4) = make_ulonglong2(o2, o3);
    }
}

// ---------------- recurrent scan (one layer, 2 rows/CTA, named bars) ----
// Grid = 128 CTAs (one per SM) x 256 threads. Row r = tid>>7 forms an
// INDEPENDENT 4-warp domain synchronized with bar.sync (r+1): two domains
// per SM overlap each other's stalls on every SMSP (2 warps/SMSP).
// Thread j holds the full Whh[j,:] row in 64 packed f32x2 regs; 8 acc
// chains. Hidden states accumulate 4 steps in regs and go out as one
// STG.128 to the TRANSPOSED [B][H][T] layout (4x fewer stores + drains).
// Final layer: no stores, FC (C=1) fused.
__global__ void __launch_bounds__(256, 1)
rnn_scan(const float* __restrict__ xp, float* __restrict__ out_h,
         const float* __restrict__ Whh, int store_all,
         const float* __restrict__ fcw, const float* __restrict__ fcb,
         float* __restrict__ fc_out) {
    __shared__ __align__(16) float hbuf[2][2][HH];  // [row][buf][j]
    __shared__ float red[2][4];

    const int tid = threadIdx.x;
    const int r = tid >> 7;
    const int j = tid & 127;
    const int b = blockIdx.x * 2 + r;

    ull w[64];
    {
        const ull* wp = (const ull*)(Whh + j * HH);
#pragma unroll
        for (int i = 0; i < 64; i++) w[i] = wp[i];
    }

    hbuf[r][0][j] = 0.f;

    const float* xptr = xp + (size_t)b * TT * HH + j;
    float* optr = out_h + (size_t)b * HH * TT + (size_t)j * TT;
    float xqa = xptr[0], xqb = xptr[HH], xqc = xptr[2 * HH];
    const float* xf = xptr + 3 * HH;  // padded scratch: safe overrun
    __syncthreads();

    float h4[4];
    float lh = 0.f;
    int buf = 0;
    for (int t = 0; t < TT; t++) {
        float xn = *xf;  // xp(t+3), lands 3 steps out
        xf += HH;

        const ulonglong2* hp = (const ulonglong2*)hbuf[r][buf];
        ull a0 = 0ULL, a1 = 0ULL, a2 = 0ULL, a3 = 0ULL;
        ull a4 = 0ULL, a5 = 0ULL, a6 = 0ULL, a7 = 0ULL;
#pragma unroll
        for (int q = 0; q < 32; q += 4) {
            ulonglong2 u0 = hp[q];      // broadcast LDS.128
            ulonglong2 u1 = hp[q + 1];
            ulonglong2 u2 = hp[q + 2];
            ulonglong2 u3 = hp[q + 3];
            ffma2(a0, u0.x, w[2 * q + 0]);
            ffma2(a1, u0.y, w[2 * q + 1]);
            ffma2(a2, u1.x, w[2 * q + 2]);
            ffma2(a3, u1.y, w[2 * q + 3]);
            ffma2(a4, u2.x, w[2 * q + 4]);
            ffma2(a5, u2.y, w[2 * q + 5]);
            ffma2(a6, u3.x, w[2 * q + 6]);
            ffma2(a7, u3.y, w[2 * q + 7]);
        }
        ull s = add2(add2(add2(a0, a1), add2(a2, a3)),
                     add2(add2(a4, a5), add2(a6, a7)));
        float2 f = *(float2*)&s;
        float h = fmaxf(f.x + f.y + xqa, 0.f);

        hbuf[r][buf ^ 1][j] = h;
        h4[t & 3] = h;
        if (store_all && (t & 3) == 3) {
            *(float4*)(optr + (t - 3)) =
                make_float4(h4[0], h4[1], h4[2], h4[3]);
        }
        lh = h;
        xqa = xqb; xqb = xqc; xqc = xn;
        buf ^= 1;
        barrow(r + 1);
    }

    if (fc_out) {
        float v = lh * fcw[j];
#pragma unroll
        for (int o = 16; o > 0; o >>= 1) v += __shfl_down_sync(0xffffffffu, v, o);
        if ((j & 31) == 0) red[r][j >> 5] = v;
        barrow(r + 1);
        if (j == 0)
            fc_out[b] = red[r][0] + red[r][1] + red[r][2] + red[r][3] + fcb[0];
    }
}

extern "C" void kernel_launch(void* const* d_in, const int* in_sizes, int n_in,
                              void* d_out, int out_size) {
    const float* x    = (const float*)d_in[0];  // [B,T,I]
    const float* Wih0 = (const float*)d_in[1];  // [H,I]
    const float* WihL = (const float*)d_in[2];  // [L-1,H,H]
    const float* Whh  = (const float*)d_in[3];  // [L,H,H]
    const float* bih  = (const float*)d_in[4];  // [L,H]
    const float* bhh  = (const float*)d_in[5];  // [L,H]
    const float* fcw  = (const float*)d_in[6];  // [C,H]
    const float* fcb  = (const float*)d_in[7];  // [C]
    float* out = (float*)d_out;                 // [B,C] = [256,1]

    float *h0, *h1, *xpb;
    cudaGetSymbolAddress((void**)&h0, g_h0);
    cudaGetSymbolAddress((void**)&h1, g_h1);
    cudaGetSymbolAddress((void**)&xpb, g_xp);

    const int HW = HH * HH;
    // layer 0
    proj0_kernel<<<(MTOT * HH) / 256, 256>>>(x, Wih0, bih, bhh, xpb);
    rnn_scan<<<BB / 2, 256>>>(xpb, h0, Whh + 0 * HW, 1, nullptr, nullptr,
                              nullptr);
    // layer 1
    gemm_xp<<<MTOT / 128, 256>>>(h0, WihL + 0 * HW, bih + 1 * HH, bhh + 1 * HH,
                                 xpb);
    rnn_scan<<<BB / 2, 256>>>(xpb, h1, Whh + 1 * HW, 1, nullptr, nullptr,
                              nullptr);
    // layer 2
    gemm_xp<<<MTOT / 128, 256>>>(h1, WihL + 1 * HW, bih + 2 * HH, bhh + 2 * HH,
                                 xpb);
    rnn_scan<<<BB / 2, 256>>>(xpb, h0, Whh + 2 * HW, 1, nullptr, nullptr,
                              nullptr);
    // layer 3: no hidden stores, FC fused
    gemm_xp<<<MTOT / 128, 256>>>(h0, WihL + 2 * HW, bih + 3 * HH, bhh + 3 * HH,
                                 xpb);
    rnn_scan<<<BB / 2, 256>>>(xpb, h1, Whh + 3 * HW, 0, fcw, fcb, out);
}